// round 12
// baseline (speedup 1.0000x reference)
#include <cuda_runtime.h>
#include <cuda_bf16.h>
#include <math.h>

#define SEQ_LEN 16384
#define ENC_H   2048
#define DEC_H   2048

#define RA      16                      // rows per fused block
#define NBLK    (SEQ_LEN / RA)          // 1024 blocks
#define VBLK    128                     // blocks that also compute v
#define RV      (ENC_H / VBLK)          // 16 v-rows per producer block

// Scratch (device globals — no allocation allowed)
__device__ float g_v[ENC_H];
__device__ float g_ctx[NBLK * ENC_H];    // 8 MB per-block partial contexts
__device__ float g_m[NBLK];
__device__ float g_z[NBLK];
__device__ unsigned int g_vdone;         // reset via cudaMemsetAsync each call

// ---------------------------------------------------------------------------
// kAll: [blocks 0..127] GEMV v-rows, flag arrive; [all blocks] spin for v,
// then single-generation fused pass (R11-proven: bulk 32 LDG.128, one
// reduction round, weights, accumulate).
// ---------------------------------------------------------------------------
__global__ __launch_bounds__(256, 1) void kAll(const float* __restrict__ enc,
                                               const float* __restrict__ W,
                                               const float* __restrict__ dec) {
    __shared__ float s_red[8][RA];
    int t    = threadIdx.x;
    int warp = t >> 5;
    int lane = t & 31;

    // ---- phase V: blocks 0..127 compute 16 rows of v = W @ dec ----
    if (blockIdx.x < VBLK) {
        size_t v0r = (size_t)blockIdx.x * RV;
        const float4* d4 = reinterpret_cast<const float4*>(dec);
        float4 u0 = __ldg(&d4[t]);
        float4 u1 = __ldg(&d4[t + 256]);

        float4 w0[RV], w1[RV];
        #pragma unroll
        for (int r = 0; r < RV; ++r) {
            const float4* row = reinterpret_cast<const float4*>(W + (v0r + r) * DEC_H);
            w0[r] = row[t];
            w1[r] = row[t + 256];
        }
        #pragma unroll
        for (int r = 0; r < RV; ++r) {
            float d = w0[r].x * u0.x + w0[r].y * u0.y + w0[r].z * u0.z + w0[r].w * u0.w
                    + w1[r].x * u1.x + w1[r].y * u1.y + w1[r].z * u1.z + w1[r].w * u1.w;
            #pragma unroll
            for (int o = 16; o > 0; o >>= 1) d += __shfl_xor_sync(0xffffffffu, d, o);
            if (lane == 0) s_red[warp][r] = d;
        }
        __syncthreads();
        if (t < RV) {
            float x = 0.0f;
            #pragma unroll
            for (int w = 0; w < 8; ++w) x += s_red[w][t];
            g_v[v0r + t] = x;
        }
        __threadfence();
        __syncthreads();
        if (t == 0) atomicAdd(&g_vdone, 1u);
        __syncthreads();               // s_red reused below
    }

    // ---- wait for complete v (producers co-resident in wave 1) ----
    if (t == 0) {
        while (atomicAdd(&g_vdone, 0u) < VBLK) __nanosleep(32);
    }
    __syncthreads();
    __threadfence();

    // ---- fused pass: 16 rows, bulk loads, one reduction round ----
    size_t s0 = (size_t)blockIdx.x * RA;
    const float4* v4 = reinterpret_cast<const float4*>(g_v);
    float4 v0 = v4[t];
    float4 v1 = v4[t + 256];

    float4 r0[RA], r1[RA];
    #pragma unroll
    for (int r = 0; r < RA; ++r) {
        const float4* row = reinterpret_cast<const float4*>(enc + (s0 + r) * ENC_H);
        r0[r] = row[t];
        r1[r] = row[t + 256];
    }

    #pragma unroll
    for (int r = 0; r < RA; ++r) {
        float d = r0[r].x * v0.x + r0[r].y * v0.y + r0[r].z * v0.z + r0[r].w * v0.w
                + r1[r].x * v1.x + r1[r].y * v1.y + r1[r].z * v1.z + r1[r].w * v1.w;
        #pragma unroll
        for (int o = 16; o > 0; o >>= 1) d += __shfl_xor_sync(0xffffffffu, d, o);
        if (lane == 0) s_red[warp][r] = d;
    }
    __syncthreads();

    float sc[RA];
    #pragma unroll
    for (int r = 0; r < RA; ++r) {
        float x = 0.0f;
        #pragma unroll
        for (int w = 0; w < 8; ++w) x += s_red[w][r];
        sc[r] = x;
    }
    float m = sc[0];
    #pragma unroll
    for (int r = 1; r < RA; ++r) m = fmaxf(m, sc[r]);
    float z = 0.0f;
    float w[RA];
    #pragma unroll
    for (int r = 0; r < RA; ++r) { w[r] = __expf(sc[r] - m); z += w[r]; }

    float4 a0 = make_float4(0.f, 0.f, 0.f, 0.f);
    float4 a1 = make_float4(0.f, 0.f, 0.f, 0.f);
    #pragma unroll
    for (int r = 0; r < RA; ++r) {
        a0.x += w[r] * r0[r].x; a0.y += w[r] * r0[r].y;
        a0.z += w[r] * r0[r].z; a0.w += w[r] * r0[r].w;
        a1.x += w[r] * r1[r].x; a1.y += w[r] * r1[r].y;
        a1.z += w[r] * r1[r].z; a1.w += w[r] * r1[r].w;
    }

    float4* ctx = reinterpret_cast<float4*>(g_ctx + (size_t)blockIdx.x * ENC_H);
    ctx[t] = a0;
    ctx[t + 256] = a1;
    if (t == 0) { g_m[blockIdx.x] = m; g_z[blockIdx.x] = z; }
}

// ---------------------------------------------------------------------------
// Kernel B: single-kernel combine over NBLK=1024 partials (R11 shape).
// ---------------------------------------------------------------------------
__global__ __launch_bounds__(256) void kB_combine(float* __restrict__ out) {
    __shared__ float s_e[NBLK];          // 4 KB
    __shared__ float s_red[8];
    __shared__ float s_M, s_invZ;
    __shared__ float4 s_out[8];
    int t    = threadIdx.x;
    int warp = t >> 5;
    int lane = t & 31;

    float m = fmaxf(g_m[t], fmaxf(g_m[t + 256], fmaxf(g_m[t + 512], g_m[t + 768])));
    #pragma unroll
    for (int o = 16; o > 0; o >>= 1) m = fmaxf(m, __shfl_xor_sync(0xffffffffu, m, o));
    if (lane == 0) s_red[warp] = m;
    __syncthreads();
    if (t == 0) {
        float mm = s_red[0];
        #pragma unroll
        for (int wdx = 1; wdx < 8; ++wdx) mm = fmaxf(mm, s_red[wdx]);
        s_M = mm;
    }
    __syncthreads();
    float M = s_M;

    float zs = 0.0f;
    #pragma unroll
    for (int i = 0; i < NBLK / 256; ++i) {
        int b = t + 256 * i;
        float e = __expf(g_m[b] - M);
        s_e[b] = e;
        zs += e * g_z[b];
    }
    #pragma unroll
    for (int o = 16; o > 0; o >>= 1) zs += __shfl_xor_sync(0xffffffffu, zs, o);
    __syncthreads();
    if (lane == 0) s_red[warp] = zs;
    __syncthreads();
    if (t == 0) {
        float s = 0.0f;
        #pragma unroll
        for (int wdx = 0; wdx < 8; ++wdx) s += s_red[wdx];
        s_invZ = 1.0f / s;
    }
    __syncthreads();

    int col4 = blockIdx.x * 4 + (warp >> 1);     // [0, 512)
    int half = warp & 1;
    const float4* ctx = reinterpret_cast<const float4*>(g_ctx);
    float4 acc = make_float4(0.f, 0.f, 0.f, 0.f);
    int b0 = half * (NBLK / 2) + lane;
    #pragma unroll 8
    for (int b = b0; b < half * (NBLK / 2) + NBLK / 2; b += 32) {
        float e  = s_e[b];
        float4 c = ctx[(size_t)b * (ENC_H / 4) + col4];
        acc.x += e * c.x; acc.y += e * c.y; acc.z += e * c.z; acc.w += e * c.w;
    }
    #pragma unroll
    for (int o = 16; o > 0; o >>= 1) {
        acc.x += __shfl_xor_sync(0xffffffffu, acc.x, o);
        acc.y += __shfl_xor_sync(0xffffffffu, acc.y, o);
        acc.z += __shfl_xor_sync(0xffffffffu, acc.z, o);
        acc.w += __shfl_xor_sync(0xffffffffu, acc.w, o);
    }
    if (lane == 0) s_out[warp] = acc;
    __syncthreads();
    if (t < 4) {
        float4 a = s_out[2 * t], b = s_out[2 * t + 1];
        float inv = s_invZ;
        float4 r;
        r.x = (a.x + b.x) * inv;
        r.y = (a.y + b.y) * inv;
        r.z = (a.z + b.z) * inv;
        r.w = (a.w + b.w) * inv;
        reinterpret_cast<float4*>(out)[blockIdx.x * 4 + t] = r;
    }
}

extern "C" void kernel_launch(void* const* d_in, const int* in_sizes, int n_in,
                              void* d_out, int out_size) {
    const float* enc = (const float*)d_in[0];   // [16384, 2048]
    const float* dec = (const float*)d_in[1];   // [1, 2048]
    const float* W   = (const float*)d_in[2];   // [2048, 2048]
    float* out = (float*)d_out;                 // [1, 2048]

    static void* vdone_addr = nullptr;
    if (!vdone_addr) cudaGetSymbolAddress(&vdone_addr, g_vdone);

    cudaMemsetAsync(vdone_addr, 0, sizeof(unsigned int));
    kAll<<<NBLK, 256>>>(enc, W, dec);
    kB_combine<<<128, 256>>>(out);
}